// round 1
// baseline (speedup 1.0000x reference)
#include <cuda_runtime.h>
#include <cuda_bf16.h>

#define NN   50000
#define INC  256
#define HH   4
#define CC   32
#define HC   128
#define OUTC 64

// ---------------- scratch (device globals; no allocs allowed) ----------------
__device__ float    g_h[NN * HC];       // 25.6 MB  transformed features
__device__ float    g_asrc[NN * HH];    // per-node attention halves
__device__ float    g_adst[NN * HH];
__device__ unsigned g_emax[NN * HH];    // order-preserving-encoded float max
__device__ float    g_denom[NN * HH];   // softmax denominators
__device__ float    g_agg[NN * HC];     // 25.6 MB  aggregated messages
__device__ int      g_is64;             // edge_index dtype flag (1 = int64)

// ---------------- helpers ----------------
__device__ __forceinline__ unsigned fenc(float f) {
    unsigned u = __float_as_uint(f);
    return (u & 0x80000000u) ? ~u : (u | 0x80000000u);
}
__device__ __forceinline__ float fdec(unsigned u) {
    unsigned b = (u & 0x80000000u) ? (u ^ 0x80000000u) : ~u;
    return __uint_as_float(b);
}
__device__ __forceinline__ void load_edge(const void* ei, int E, int e, int& s, int& d) {
    if (e >= E) { s = d = e - E; return; }          // self loop
    if (g_is64) {
        const long long* p = (const long long*)ei;
        s = (int)p[e]; d = (int)p[E + e];
    } else {
        const int* p = (const int*)ei;
        s = p[e]; d = p[E + e];
    }
}
__device__ __forceinline__ void red_add_v4(float* p, float a, float b, float c, float d) {
    asm volatile("red.global.add.v4.f32 [%0], {%1, %2, %3, %4};"
                 :: "l"(p), "f"(a), "f"(b), "f"(c), "f"(d) : "memory");
}

// ---------------- dtype detection: int32 read as int64 -> huge values ----------------
__global__ void detect_kernel(const long long* ei) {
    if (blockIdx.x == 0 && threadIdx.x == 0) {
        int ok64 = 1;
        #pragma unroll
        for (int i = 0; i < 16; i++) {
            long long v = ei[i];
            if (v < 0 || v >= (long long)NN) { ok64 = 0; break; }
        }
        g_is64 = ok64;
    }
}

// ---------------- GEMM1: h = x @ W   [N,256]x[256,128] ----------------
__global__ void gemm1_kernel(const float* __restrict__ x, const float* __restrict__ W) {
    __shared__ float Xs[16][65];   // [k][row], padded
    __shared__ float Ws[16][128];  // [k][col]
    int t    = threadIdx.x;
    int row0 = blockIdx.x * 64;
    int r0   = (t >> 5) * 8;       // 8 rows per thread
    int c0   = (t & 31) * 4;       // 4 cols per thread
    float acc[8][4];
    #pragma unroll
    for (int i = 0; i < 8; i++)
        #pragma unroll
        for (int j = 0; j < 4; j++) acc[i][j] = 0.f;

    for (int k0 = 0; k0 < INC; k0 += 16) {
        for (int i = t; i < 64 * 16; i += 256) {
            int m = i >> 4, k = i & 15;
            int row = row0 + m;
            Xs[k][m] = (row < NN) ? x[row * INC + k0 + k] : 0.f;
        }
        for (int i = t; i < 16 * 128; i += 256) {
            int k = i >> 7, n = i & 127;
            Ws[k][n] = W[(k0 + k) * HC + n];
        }
        __syncthreads();
        #pragma unroll
        for (int k = 0; k < 16; k++) {
            float4 w = *(const float4*)&Ws[k][c0];
            float a[8];
            #pragma unroll
            for (int i = 0; i < 8; i++) a[i] = Xs[k][r0 + i];
            #pragma unroll
            for (int i = 0; i < 8; i++) {
                acc[i][0] += a[i] * w.x; acc[i][1] += a[i] * w.y;
                acc[i][2] += a[i] * w.z; acc[i][3] += a[i] * w.w;
            }
        }
        __syncthreads();
    }
    #pragma unroll
    for (int i = 0; i < 8; i++) {
        int row = row0 + r0 + i;
        if (row < NN) {
            float4 v = make_float4(acc[i][0], acc[i][1], acc[i][2], acc[i][3]);
            *(float4*)&g_h[row * HC + c0] = v;
        }
    }
}

// ---------------- per-node attention halves: warp per node ----------------
__global__ void att_kernel(const float* __restrict__ att_src, const float* __restrict__ att_dst) {
    int gid  = blockIdx.x * blockDim.x + threadIdx.x;
    int node = gid >> 5;
    int lane = gid & 31;
    if (node >= NN) return;
    float4 hv = *(const float4*)&g_h[node * HC + lane * 4];
    float4 as = *(const float4*)&att_src[lane * 4];   // [H,C] flattened = 128
    float4 ad = *(const float4*)&att_dst[lane * 4];
    float ps = hv.x * as.x + hv.y * as.y + hv.z * as.z + hv.w * as.w;
    float pd = hv.x * ad.x + hv.y * ad.y + hv.z * ad.z + hv.w * ad.w;
    // reduce within 8-lane groups (one head per 8 lanes)
    #pragma unroll
    for (int o = 4; o > 0; o >>= 1) {
        ps += __shfl_down_sync(0xffffffffu, ps, o);
        pd += __shfl_down_sync(0xffffffffu, pd, o);
    }
    if ((lane & 7) == 0) {
        int h = lane >> 3;
        g_asrc[node * HH + h] = ps;
        g_adst[node * HH + h] = pd;
    }
}

// ---------------- init: zero agg/denom, emax = enc(-inf) ----------------
__global__ void init_kernel() {
    int i = blockIdx.x * blockDim.x + threadIdx.x;
    if (i < NN * HC) g_agg[i] = 0.f;
    if (i < NN * HH) { g_denom[i] = 0.f; g_emax[i] = 0x007FFFFFu; }
}

// ---------------- pass 1: segment max (atomicMax on encoded float) ----------------
__global__ void emax_kernel(const void* __restrict__ ei, int E) {
    int e = blockIdx.x * blockDim.x + threadIdx.x;
    int ET = E + NN;
    if (e >= ET) return;
    int s, d;
    load_edge(ei, E, e, s, d);
    float4 as = *(const float4*)&g_asrc[s * HH];
    float4 ad = *(const float4*)&g_adst[d * HH];
    float v[4] = { as.x + ad.x, as.y + ad.y, as.z + ad.z, as.w + ad.w };
    #pragma unroll
    for (int h = 0; h < 4; h++) {
        float lv = v[h] > 0.f ? v[h] : 0.2f * v[h];
        atomicMax(&g_emax[d * HH + h], fenc(lv));
    }
}

// ---------------- pass 2: softmax denominators ----------------
__global__ void denom_kernel(const void* __restrict__ ei, int E) {
    int e = blockIdx.x * blockDim.x + threadIdx.x;
    int ET = E + NN;
    if (e >= ET) return;
    int s, d;
    load_edge(ei, E, e, s, d);
    float4 as = *(const float4*)&g_asrc[s * HH];
    float4 ad = *(const float4*)&g_adst[d * HH];
    float v[4] = { as.x + ad.x, as.y + ad.y, as.z + ad.z, as.w + ad.w };
    float ex[4];
    #pragma unroll
    for (int h = 0; h < 4; h++) {
        float lv = v[h] > 0.f ? v[h] : 0.2f * v[h];
        float m  = fdec(g_emax[d * HH + h]);
        ex[h] = __expf(lv - m);
    }
    red_add_v4(&g_denom[d * HH], ex[0], ex[1], ex[2], ex[3]);
}

// ---------------- pass 3: weighted scatter, warp per edge ----------------
__global__ void scatter_kernel(const void* __restrict__ ei, int E) {
    int gid  = blockIdx.x * blockDim.x + threadIdx.x;
    int e    = gid >> 5;
    int lane = gid & 31;
    int ET = E + NN;
    if (e >= ET) return;
    int s, d;
    load_edge(ei, E, e, s, d);
    int h = lane >> 3;                       // head for this lane's float4
    float av = g_asrc[s * HH + h] + g_adst[d * HH + h];
    av = av > 0.f ? av : 0.2f * av;
    float m   = fdec(g_emax[d * HH + h]);
    float den = g_denom[d * HH + h];
    float alpha = __expf(av - m) / den;
    float4 hv = *(const float4*)&g_h[s * HC + lane * 4];
    red_add_v4(&g_agg[d * HC + lane * 4],
               alpha * hv.x, alpha * hv.y, alpha * hv.z, alpha * hv.w);
}

// ---------------- GEMM2: out = elu(agg + bias) @ lin_W + lin_b ----------------
__global__ void gemm2_kernel(const float* __restrict__ bias, const float* __restrict__ linW,
                             const float* __restrict__ linb, float* __restrict__ out) {
    __shared__ float As[16][65];        // [k][row]
    __shared__ float Ws[HC][OUTC];      // full lin_W, 32 KB
    int t    = threadIdx.x;
    int row0 = blockIdx.x * 64;
    for (int i = t; i < HC * OUTC; i += 256) Ws[i >> 6][i & 63] = linW[i];
    int r0 = (t >> 4) * 4;              // 4 rows per thread
    int c0 = (t & 15) * 4;              // 4 cols per thread
    float acc[4][4];
    #pragma unroll
    for (int i = 0; i < 4; i++)
        #pragma unroll
        for (int j = 0; j < 4; j++) acc[i][j] = 0.f;

    for (int k0 = 0; k0 < HC; k0 += 16) {
        for (int i = t; i < 64 * 16; i += 256) {
            int m = i >> 4, k = i & 15;
            int row = row0 + m;
            float v = 0.f;
            if (row < NN) {
                v = g_agg[row * HC + k0 + k] + bias[k0 + k];
                v = v > 0.f ? v : expm1f(v);
            }
            As[k][m] = v;
        }
        __syncthreads();                // also covers Ws on first iteration
        #pragma unroll
        for (int k = 0; k < 16; k++) {
            float4 w = *(const float4*)&Ws[k0 + k][c0];
            float a[4];
            #pragma unroll
            for (int i = 0; i < 4; i++) a[i] = As[k][r0 + i];
            #pragma unroll
            for (int i = 0; i < 4; i++) {
                acc[i][0] += a[i] * w.x; acc[i][1] += a[i] * w.y;
                acc[i][2] += a[i] * w.z; acc[i][3] += a[i] * w.w;
            }
        }
        __syncthreads();
    }
    float4 b4 = *(const float4*)&linb[c0];
    #pragma unroll
    for (int i = 0; i < 4; i++) {
        int row = row0 + r0 + i;
        if (row < NN) {
            float4 v = make_float4(acc[i][0] + b4.x, acc[i][1] + b4.y,
                                   acc[i][2] + b4.z, acc[i][3] + b4.w);
            *(float4*)&out[row * OUTC + c0] = v;
        }
    }
}

// ---------------- launcher ----------------
extern "C" void kernel_launch(void* const* d_in, const int* in_sizes, int n_in,
                              void* d_out, int out_size) {
    const float* x        = (const float*)d_in[0];
    const void*  ei       = d_in[1];
    const float* W        = (const float*)d_in[2];
    const float* att_src  = (const float*)d_in[3];
    const float* att_dst  = (const float*)d_in[4];
    const float* bias     = (const float*)d_in[5];
    const float* linW     = (const float*)d_in[6];
    const float* linb     = (const float*)d_in[7];
    float*       out      = (float*)d_out;

    int E  = in_sizes[1] / 2;
    int ET = E + NN;

    detect_kernel<<<1, 32>>>((const long long*)ei);
    init_kernel<<<(NN * HC + 255) / 256, 256>>>();
    gemm1_kernel<<<(NN + 63) / 64, 256>>>(x, W);
    att_kernel<<<(NN * 32 + 255) / 256, 256>>>(att_src, att_dst);
    emax_kernel<<<(ET + 255) / 256, 256>>>(ei, E);
    denom_kernel<<<(ET + 255) / 256, 256>>>(ei, E);
    {
        long long total = (long long)ET * 32;
        int blocks = (int)((total + 255) / 256);
        scatter_kernel<<<blocks, 256>>>(ei, E);
    }
    gemm2_kernel<<<(NN + 63) / 64, 256>>>(bias, linW, linb, out);
}

// round 5
// speedup vs baseline: 1.4937x; 1.4937x over previous
#include <cuda_runtime.h>
#include <cuda_bf16.h>

#define NN    50000
#define INC   256
#define HH    4
#define HC    128
#define OUTC  64
#define EMAX  1700000   // capacity for E + self loops

// ---------------- scratch (device globals; no allocs allowed) ----------------
__device__ float g_h[NN * HC];          // transformed features (25.6 MB)
__device__ float g_asrc[NN * HH];
__device__ float g_adst[NN * HH];
__device__ float g_agg[NN * HC];        // elu(agg+bias), ready for gemm2
__device__ int   g_cnt[NN];             // in-degree (incl self loop)
__device__ int   g_off[NN + 1];         // CSR offsets
__device__ int   g_cur[NN];             // fill cursors
__device__ int   g_srcidx[EMAX + NN];   // CSR column (source) indices
__device__ int   g_is64;                // edge dtype flag

// ---------------- helpers ----------------
__device__ __forceinline__ void load_edge(const void* ei, int E, int e, int& s, int& d) {
    if (e >= E) { s = d = e - E; return; }          // self loop
    if (g_is64) {
        const long long* p = (const long long*)ei;
        s = (int)p[e]; d = (int)p[E + e];
    } else {
        const int* p = (const int*)ei;
        s = p[e]; d = p[E + e];
    }
}

// ---------------- fused: dtype detect (block 0) + degree init ----------------
__global__ void prep_kernel(const long long* ei) {
    int i = blockIdx.x * blockDim.x + threadIdx.x;
    if (i == 0) {
        int ok64 = 1;
        #pragma unroll
        for (int j = 0; j < 16; j++) {
            long long v = ei[j];
            if (v < 0 || v >= (long long)NN) { ok64 = 0; break; }
        }
        g_is64 = ok64;
    }
    if (i < NN) g_cnt[i] = 1;           // self loop
}

// ---------------- GEMM1: h = x @ W   [N,256]x[256,128], 128x128 tile ----------------
__global__ void __launch_bounds__(256) gemm1_kernel(const float* __restrict__ x,
                                                    const float* __restrict__ W) {
    __shared__ float Xs[16][136];   // [k][row], padded
    __shared__ float Ws[16][128];   // [k][col]
    int t    = threadIdx.x;
    int row0 = blockIdx.x * 128;
    int tx   = t & 15, ty = t >> 4;
    int r0   = ty * 8;
    int c0   = tx * 8;
    float acc[8][8];
    #pragma unroll
    for (int i = 0; i < 8; i++)
        #pragma unroll
        for (int j = 0; j < 8; j++) acc[i][j] = 0.f;

    for (int k0 = 0; k0 < INC; k0 += 16) {
        #pragma unroll
        for (int i = t; i < 512; i += 256) {
            int row = i >> 2, kq = (i & 3) * 4;
            float4 v = make_float4(0.f, 0.f, 0.f, 0.f);
            int gr = row0 + row;
            if (gr < NN) v = *(const float4*)&x[gr * INC + k0 + kq];
            Xs[kq + 0][row] = v.x; Xs[kq + 1][row] = v.y;
            Xs[kq + 2][row] = v.z; Xs[kq + 3][row] = v.w;
        }
        #pragma unroll
        for (int i = t; i < 512; i += 256) {
            int k = i >> 5, nq = (i & 31) * 4;
            *(float4*)&Ws[k][nq] = *(const float4*)&W[(k0 + k) * HC + nq];
        }
        __syncthreads();
        #pragma unroll
        for (int k = 0; k < 16; k++) {
            float4 a0 = *(const float4*)&Xs[k][r0];
            float4 a1 = *(const float4*)&Xs[k][r0 + 4];
            float4 b0 = *(const float4*)&Ws[k][c0];
            float4 b1 = *(const float4*)&Ws[k][c0 + 4];
            float av[8] = { a0.x, a0.y, a0.z, a0.w, a1.x, a1.y, a1.z, a1.w };
            float bv[8] = { b0.x, b0.y, b0.z, b0.w, b1.x, b1.y, b1.z, b1.w };
            #pragma unroll
            for (int i = 0; i < 8; i++)
                #pragma unroll
                for (int j = 0; j < 8; j++)
                    acc[i][j] += av[i] * bv[j];
        }
        __syncthreads();
    }
    #pragma unroll
    for (int i = 0; i < 8; i++) {
        int row = row0 + r0 + i;
        if (row < NN) {
            *(float4*)&g_h[row * HC + c0]     = make_float4(acc[i][0], acc[i][1], acc[i][2], acc[i][3]);
            *(float4*)&g_h[row * HC + c0 + 4] = make_float4(acc[i][4], acc[i][5], acc[i][6], acc[i][7]);
        }
    }
}

// ---------------- per-node attention halves: warp per node ----------------
__global__ void att_kernel(const float* __restrict__ att_src, const float* __restrict__ att_dst) {
    int gid  = blockIdx.x * blockDim.x + threadIdx.x;
    int node = gid >> 5;
    int lane = gid & 31;
    if (node >= NN) return;
    float4 hv = *(const float4*)&g_h[node * HC + lane * 4];
    float4 as = *(const float4*)&att_src[lane * 4];
    float4 ad = *(const float4*)&att_dst[lane * 4];
    float ps = hv.x * as.x + hv.y * as.y + hv.z * as.z + hv.w * as.w;
    float pd = hv.x * ad.x + hv.y * ad.y + hv.z * ad.z + hv.w * ad.w;
    #pragma unroll
    for (int o = 4; o > 0; o >>= 1) {
        ps += __shfl_down_sync(0xffffffffu, ps, o);
        pd += __shfl_down_sync(0xffffffffu, pd, o);
    }
    if ((lane & 7) == 0) {
        int h = lane >> 3;
        g_asrc[node * HH + h] = ps;
        g_adst[node * HH + h] = pd;
    }
}

// ---------------- CSR build: histogram ----------------
__global__ void hist_kernel(const void* __restrict__ ei, int E) {
    int e = blockIdx.x * blockDim.x + threadIdx.x;
    if (e >= E) return;
    int d;
    if (g_is64) d = (int)((const long long*)ei)[E + e];
    else        d = ((const int*)ei)[E + e];
    atomicAdd(&g_cnt[d], 1);
}

// ---------------- CSR build: single-block exclusive scan ----------------
__global__ void __launch_bounds__(1024) scan_kernel() {
    __shared__ int partial[1024];
    const int PER = (NN + 1023) / 1024;     // 49
    int t = threadIdx.x;
    int base = t * PER;
    int sum = 0;
    for (int i = 0; i < PER; i++) {
        int idx = base + i;
        if (idx < NN) sum += g_cnt[idx];
    }
    partial[t] = sum;
    __syncthreads();
    for (int off = 1; off < 1024; off <<= 1) {
        int v = (t >= off) ? partial[t - off] : 0;
        __syncthreads();
        partial[t] += v;
        __syncthreads();
    }
    int run = partial[t] - sum;
    for (int i = 0; i < PER; i++) {
        int idx = base + i;
        if (idx < NN) {
            int c = g_cnt[idx];
            g_off[idx] = run;
            g_cur[idx] = run;
            run += c;
        }
    }
    if (t == 1023) g_off[NN] = partial[1023];
}

// ---------------- CSR build: fill (edges + self loops) ----------------
__global__ void fill_kernel(const void* __restrict__ ei, int E) {
    int e = blockIdx.x * blockDim.x + threadIdx.x;
    int ET = E + NN;
    if (e >= ET) return;
    int s, d;
    load_edge(ei, E, e, s, d);
    int pos = atomicAdd(&g_cur[d], 1);
    g_srcidx[pos] = s;
}

// ---------------- fused gather: softmax + weighted sum + bias + ELU ----------------
// warp per destination node; lane owns 4 feature channels; head = lane>>3.
// Two CSR entries processed per iteration; all loads for both issued up front
// to keep ~6-8 independent loads in flight per lane (MLP against L2 latency).
__global__ void gather_kernel(const float* __restrict__ bias) {
    int gid  = blockIdx.x * blockDim.x + threadIdx.x;
    int node = gid >> 5;
    int lane = gid & 31;
    if (node >= NN) return;
    int beg = g_off[node], end = g_off[node + 1];
    int h = lane >> 3;
    float adst = g_adst[node * HH + h];
    float a0 = 0.f, a1 = 0.f, a2 = 0.f, a3 = 0.f, den = 0.f;

    int k = beg;
    // pairwise main loop
    for (; k + 1 < end; k += 2) {
        int sA = __ldg(&g_srcidx[k]);
        int sB = __ldg(&g_srcidx[k + 1]);
        float asA = __ldg(&g_asrc[sA * HH + h]);
        float asB = __ldg(&g_asrc[sB * HH + h]);
        float4 hA = *(const float4*)&g_h[sA * HC + lane * 4];
        float4 hB = *(const float4*)&g_h[sB * HC + lane * 4];
        float avA = asA + adst; avA = avA > 0.f ? avA : 0.2f * avA;
        float avB = asB + adst; avB = avB > 0.f ? avB : 0.2f * avB;
        float exA = __expf(avA);
        float exB = __expf(avB);
        a0 += exA * hA.x + exB * hB.x;
        a1 += exA * hA.y + exB * hB.y;
        a2 += exA * hA.z + exB * hB.z;
        a3 += exA * hA.w + exB * hB.w;
        den += exA + exB;
    }
    if (k < end) {
        int sA = __ldg(&g_srcidx[k]);
        float asA = __ldg(&g_asrc[sA * HH + h]);
        float4 hA = *(const float4*)&g_h[sA * HC + lane * 4];
        float avA = asA + adst; avA = avA > 0.f ? avA : 0.2f * avA;
        float exA = __expf(avA);
        a0 += exA * hA.x; a1 += exA * hA.y; a2 += exA * hA.z; a3 += exA * hA.w;
        den += exA;
    }

    float inv = 1.f / den;                   // self loop guarantees den > 0
    float4 b = *(const float4*)&bias[lane * 4];
    float v0 = a0 * inv + b.x, v1 = a1 * inv + b.y;
    float v2 = a2 * inv + b.z, v3 = a3 * inv + b.w;
    v0 = v0 > 0.f ? v0 : expm1f(v0);
    v1 = v1 > 0.f ? v1 : expm1f(v1);
    v2 = v2 > 0.f ? v2 : expm1f(v2);
    v3 = v3 > 0.f ? v3 : expm1f(v3);
    *(float4*)&g_agg[node * HC + lane * 4] = make_float4(v0, v1, v2, v3);
}

// ---------------- GEMM2: out = g_agg @ lin_W + lin_b ----------------
__global__ void __launch_bounds__(256) gemm2_kernel(const float* __restrict__ linW,
                                                    const float* __restrict__ linb,
                                                    float* __restrict__ out) {
    __shared__ float As[16][65];
    __shared__ float Ws[HC][OUTC];
    int t    = threadIdx.x;
    int row0 = blockIdx.x * 64;
    for (int i = t; i < HC * OUTC; i += 256) Ws[i >> 6][i & 63] = linW[i];
    int r0 = (t >> 4) * 4;
    int c0 = (t & 15) * 4;
    float acc[4][4];
    #pragma unroll
    for (int i = 0; i < 4; i++)
        #pragma unroll
        for (int j = 0; j < 4; j++) acc[i][j] = 0.f;

    for (int k0 = 0; k0 < HC; k0 += 16) {
        for (int i = t; i < 64 * 16; i += 256) {
            int m = i >> 4, k = i & 15;
            int row = row0 + m;
            As[k][m] = (row < NN) ? g_agg[row * HC + k0 + k] : 0.f;
        }
        __syncthreads();
        #pragma unroll
        for (int k = 0; k < 16; k++) {
            float4 w = *(const float4*)&Ws[k0 + k][c0];
            float a[4];
            #pragma unroll
            for (int i = 0; i < 4; i++) a[i] = As[k][r0 + i];
            #pragma unroll
            for (int i = 0; i < 4; i++) {
                acc[i][0] += a[i] * w.x; acc[i][1] += a[i] * w.y;
                acc[i][2] += a[i] * w.z; acc[i][3] += a[i] * w.w;
            }
        }
        __syncthreads();
    }
    float4 b4 = *(const float4*)&linb[c0];
    #pragma unroll
    for (int i = 0; i < 4; i++) {
        int row = row0 + r0 + i;
        if (row < NN) {
            *(float4*)&out[row * OUTC + c0] = make_float4(acc[i][0] + b4.x, acc[i][1] + b4.y,
                                                          acc[i][2] + b4.z, acc[i][3] + b4.w);
        }
    }
}

// ---------------- launcher ----------------
extern "C" void kernel_launch(void* const* d_in, const int* in_sizes, int n_in,
                              void* d_out, int out_size) {
    const float* x       = (const float*)d_in[0];
    const void*  ei      = d_in[1];
    const float* W       = (const float*)d_in[2];
    const float* att_src = (const float*)d_in[3];
    const float* att_dst = (const float*)d_in[4];
    const float* bias    = (const float*)d_in[5];
    const float* linW    = (const float*)d_in[6];
    const float* linb    = (const float*)d_in[7];
    float*       out     = (float*)d_out;

    int E  = in_sizes[1] / 2;
    int ET = E + NN;

    prep_kernel<<<(NN + 255) / 256, 256>>>((const long long*)ei);
    hist_kernel<<<(E + 255) / 256, 256>>>(ei, E);
    scan_kernel<<<1, 1024>>>();
    fill_kernel<<<(ET + 255) / 256, 256>>>(ei, E);
    gemm1_kernel<<<(NN + 127) / 128, 256>>>(x, W);
    att_kernel<<<(NN * 32 + 255) / 256, 256>>>(att_src, att_dst);
    gather_kernel<<<(NN * 32 + 255) / 256, 256>>>(bias);
    gemm2_kernel<<<(NN + 63) / 64, 256>>>(linW, linb, out);
}

// round 8
// speedup vs baseline: 1.5155x; 1.0146x over previous
#include <cuda_runtime.h>
#include <cuda_fp16.h>

#define NN    50000
#define INC   256
#define HH    4
#define HC    128
#define OUTC  64
#define EMAX  1700000   // capacity for E + self loops

// ---------------- scratch (device globals; no allocs allowed) ----------------
__device__ __half g_h16[NN * HC];       // transformed features, fp16 (12.8 MB)
__device__ float  g_asrc[NN * HH];
__device__ float  g_adst[NN * HH];
__device__ float  g_agg[NN * HC];       // elu(agg+bias), ready for gemm2
__device__ int    g_cnt[NN];            // in-degree (incl self loop)
__device__ int    g_off[NN + 1];        // CSR offsets
__device__ int    g_cur[NN];            // fill cursors
__device__ int    g_srcidx[EMAX + NN];  // CSR column (source) indices
__device__ int    g_is64;               // edge dtype flag

// ---------------- fused: dtype detect (thread 0) + degree init ----------------
__global__ void prep_kernel(const long long* ei) {
    int i = blockIdx.x * blockDim.x + threadIdx.x;
    if (i == 0) {
        int ok64 = 1;
        #pragma unroll
        for (int j = 0; j < 16; j++) {
            long long v = ei[j];
            if (v < 0 || v >= (long long)NN) { ok64 = 0; break; }
        }
        g_is64 = ok64;
    }
    if (i < NN) g_cnt[i] = 1;           // self loop
}

// ---------------- GEMM1 + fused attention halves ----------------
// h = x @ W  [N,256]x[256,128]; h stored fp16; a_src/a_dst computed from the
// fp32 accumulators in-register (each thread's 8 cols lie inside ONE head).
__global__ void __launch_bounds__(256) gemm1_kernel(const float* __restrict__ x,
                                                    const float* __restrict__ W,
                                                    const float* __restrict__ att_src,
                                                    const float* __restrict__ att_dst) {
    __shared__ float Xs[16][136];   // [k][row], padded
    __shared__ float Ws[16][128];   // [k][col]
    int t    = threadIdx.x;
    int row0 = blockIdx.x * 128;
    int tx   = t & 15, ty = t >> 4;
    int r0   = ty * 8;
    int c0   = tx * 8;
    float acc[8][8];
    #pragma unroll
    for (int i = 0; i < 8; i++)
        #pragma unroll
        for (int j = 0; j < 8; j++) acc[i][j] = 0.f;

    for (int k0 = 0; k0 < INC; k0 += 16) {
        #pragma unroll
        for (int i = t; i < 512; i += 256) {
            int row = i >> 2, kq = (i & 3) * 4;
            float4 v = make_float4(0.f, 0.f, 0.f, 0.f);
            int gr = row0 + row;
            if (gr < NN) v = *(const float4*)&x[gr * INC + k0 + kq];
            Xs[kq + 0][row] = v.x; Xs[kq + 1][row] = v.y;
            Xs[kq + 2][row] = v.z; Xs[kq + 3][row] = v.w;
        }
        #pragma unroll
        for (int i = t; i < 512; i += 256) {
            int k = i >> 5, nq = (i & 31) * 4;
            *(float4*)&Ws[k][nq] = *(const float4*)&W[(k0 + k) * HC + nq];
        }
        __syncthreads();
        #pragma unroll
        for (int k = 0; k < 16; k++) {
            float4 a0 = *(const float4*)&Xs[k][r0];
            float4 a1 = *(const float4*)&Xs[k][r0 + 4];
            float4 b0 = *(const float4*)&Ws[k][c0];
            float4 b1 = *(const float4*)&Ws[k][c0 + 4];
            float av[8] = { a0.x, a0.y, a0.z, a0.w, a1.x, a1.y, a1.z, a1.w };
            float bv[8] = { b0.x, b0.y, b0.z, b0.w, b1.x, b1.y, b1.z, b1.w };
            #pragma unroll
            for (int i = 0; i < 8; i++)
                #pragma unroll
                for (int j = 0; j < 8; j++)
                    acc[i][j] += av[i] * bv[j];
        }
        __syncthreads();
    }

    // ---- epilogue 1: store h as fp16 (8 halves = 16B per row-chunk) ----
    #pragma unroll
    for (int i = 0; i < 8; i++) {
        int row = row0 + r0 + i;
        if (row < NN) {
            __half2 p0 = __floats2half2_rn(acc[i][0], acc[i][1]);
            __half2 p1 = __floats2half2_rn(acc[i][2], acc[i][3]);
            __half2 p2 = __floats2half2_rn(acc[i][4], acc[i][5]);
            __half2 p3 = __floats2half2_rn(acc[i][6], acc[i][7]);
            uint4 pk;
            pk.x = *(unsigned*)&p0; pk.y = *(unsigned*)&p1;
            pk.z = *(unsigned*)&p2; pk.w = *(unsigned*)&p3;
            *(uint4*)&g_h16[row * HC + c0] = pk;
        }
    }

    // ---- epilogue 2: attention halves from registers ----
    // cols c0..c0+7 all lie in head hd = tx>>2; 4 lanes (tx&3 = 0..3) cover the head.
    int hd = tx >> 2;
    float asv[8], adv[8];
    #pragma unroll
    for (int j = 0; j < 8; j++) { asv[j] = att_src[c0 + j]; adv[j] = att_dst[c0 + j]; }
    #pragma unroll
    for (int i = 0; i < 8; i++) {
        float ps = 0.f, pd = 0.f;
        #pragma unroll
        for (int j = 0; j < 8; j++) { ps += acc[i][j] * asv[j]; pd += acc[i][j] * adv[j]; }
        ps += __shfl_down_sync(0xffffffffu, ps, 2);
        ps += __shfl_down_sync(0xffffffffu, ps, 1);
        pd += __shfl_down_sync(0xffffffffu, pd, 2);
        pd += __shfl_down_sync(0xffffffffu, pd, 1);
        int row = row0 + r0 + i;
        if ((tx & 3) == 0 && row < NN) {
            g_asrc[row * HH + hd] = ps;
            g_adst[row * HH + hd] = pd;
        }
    }
}

// ---------------- CSR build: histogram, 4 edges/thread for MLP ----------------
__global__ void hist_kernel(const void* __restrict__ ei, int E) {
    int base = (blockIdx.x * blockDim.x + threadIdx.x) * 4;
    if (base >= E) return;
    int d[4]; int n = min(4, E - base);
    if (g_is64) {
        const long long* p = (const long long*)ei + E;
        #pragma unroll
        for (int i = 0; i < 4; i++) if (i < n) d[i] = (int)p[base + i];
    } else {
        const int* p = (const int*)ei + E;
        #pragma unroll
        for (int i = 0; i < 4; i++) if (i < n) d[i] = p[base + i];
    }
    #pragma unroll
    for (int i = 0; i < 4; i++) if (i < n) atomicAdd(&g_cnt[d[i]], 1);
}

// ---------------- CSR build: single-block exclusive scan ----------------
__global__ void __launch_bounds__(1024) scan_kernel() {
    __shared__ int partial[1024];
    const int PER = (NN + 1023) / 1024;     // 49
    int t = threadIdx.x;
    int base = t * PER;
    int sum = 0;
    for (int i = 0; i < PER; i++) {
        int idx = base + i;
        if (idx < NN) sum += g_cnt[idx];
    }
    partial[t] = sum;
    __syncthreads();
    for (int off = 1; off < 1024; off <<= 1) {
        int v = (t >= off) ? partial[t - off] : 0;
        __syncthreads();
        partial[t] += v;
        __syncthreads();
    }
    int run = partial[t] - sum;
    for (int i = 0; i < PER; i++) {
        int idx = base + i;
        if (idx < NN) {
            int c = g_cnt[idx];
            g_off[idx] = run;
            g_cur[idx] = run;
            run += c;
        }
    }
    if (t == 1023) g_off[NN] = partial[1023];
}

// ---------------- CSR build: fill, 4 edges/thread for MLP ----------------
__global__ void fill_kernel(const void* __restrict__ ei, int E) {
    int ET = E + NN;
    int base = (blockIdx.x * blockDim.x + threadIdx.x) * 4;
    if (base >= ET) return;
    int n = min(4, ET - base);
    int s[4], d[4];
    if (g_is64) {
        const long long* ps = (const long long*)ei;
        const long long* pd = ps + E;
        #pragma unroll
        for (int i = 0; i < 4; i++) if (i < n) {
            int e = base + i;
            if (e >= E) { s[i] = d[i] = e - E; }
            else        { s[i] = (int)ps[e]; d[i] = (int)pd[e]; }
        }
    } else {
        const int* ps = (const int*)ei;
        const int* pd = ps + E;
        #pragma unroll
        for (int i = 0; i < 4; i++) if (i < n) {
            int e = base + i;
            if (e >= E) { s[i] = d[i] = e - E; }
            else        { s[i] = ps[e]; d[i] = pd[e]; }
        }
    }
    int pos[4];
    #pragma unroll
    for (int i = 0; i < 4; i++) if (i < n) pos[i] = atomicAdd(&g_cur[d[i]], 1);
    #pragma unroll
    for (int i = 0; i < 4; i++) if (i < n) g_srcidx[pos[i]] = s[i];
}

// ---------------- fused gather: softmax + weighted sum + bias + ELU ----------------
// warp per destination node; lane owns 4 feature channels (8B fp16); head = lane>>3.
__global__ void gather_kernel(const float* __restrict__ bias) {
    int gid  = blockIdx.x * blockDim.x + threadIdx.x;
    int node = gid >> 5;
    int lane = gid & 31;
    if (node >= NN) return;
    int beg = g_off[node], end = g_off[node + 1];
    int h = lane >> 3;
    float adst = g_adst[node * HH + h];
    float a0 = 0.f, a1 = 0.f, a2 = 0.f, a3 = 0.f, den = 0.f;

    int k = beg;
    for (; k + 1 < end; k += 2) {
        int sA = __ldg(&g_srcidx[k]);
        int sB = __ldg(&g_srcidx[k + 1]);
        float asA = __ldg(&g_asrc[sA * HH + h]);
        float asB = __ldg(&g_asrc[sB * HH + h]);
        uint2 rA = *(const uint2*)&g_h16[sA * HC + lane * 4];
        uint2 rB = *(const uint2*)&g_h16[sB * HC + lane * 4];
        float2 hA0 = __half22float2(*(__half2*)&rA.x);
        float2 hA1 = __half22float2(*(__half2*)&rA.y);
        float2 hB0 = __half22float2(*(__half2*)&rB.x);
        float2 hB1 = __half22float2(*(__half2*)&rB.y);
        float avA = asA + adst; avA = avA > 0.f ? avA : 0.2f * avA;
        float avB = asB + adst; avB = avB > 0.f ? avB : 0.2f * avB;
        float exA = __expf(avA);
        float exB = __expf(avB);
        a0 += exA * hA0.x + exB * hB0.x;
        a1 += exA * hA0.y + exB * hB0.y;
        a2 += exA * hA1.x + exB * hB1.x;
        a3 += exA * hA1.y + exB * hB1.y;
        den += exA + exB;
    }
    if (k < end) {
        int sA = __ldg(&g_srcidx[k]);
        float asA = __ldg(&g_asrc[sA * HH + h]);
        uint2 rA = *(const uint2*)&g_h16[sA * HC + lane * 4];
        float2 hA0 = __half22float2(*(__half2*)&rA.x);
        float2 hA1 = __half22float2(*(__half2*)&rA.y);
        float avA = asA + adst; avA = avA > 0.f ? avA : 0.2f * avA;
        float exA = __expf(avA);
        a0 += exA * hA0.x; a1 += exA * hA0.y; a2 += exA * hA1.x; a3 += exA * hA1.y;
        den += exA;
    }

    float inv = 1.f / den;                   // self loop guarantees den > 0
    float4 b = *(const float4*)&bias[lane * 4];
    float v0 = a0 * inv + b.x, v1 = a1 * inv + b.y;
    float v2 = a2 * inv + b.z, v3 = a3 * inv + b.w;
    v0 = v0 > 0.f ? v0 : expm1f(v0);
    v1 = v1 > 0.f ? v1 : expm1f(v1);
    v2 = v2 > 0.f ? v2 : expm1f(v2);
    v3 = v3 > 0.f ? v3 : expm1f(v3);
    *(float4*)&g_agg[node * HC + lane * 4] = make_float4(v0, v1, v2, v3);
}

// ---------------- GEMM2: out = g_agg @ lin_W + lin_b ----------------
__global__ void __launch_bounds__(256) gemm2_kernel(const float* __restrict__ linW,
                                                    const float* __restrict__ linb,
                                                    float* __restrict__ out) {
    __shared__ float As[16][65];
    __shared__ float Ws[HC][OUTC];
    int t    = threadIdx.x;
    int row0 = blockIdx.x * 64;
    for (int i = t; i < HC * OUTC; i += 256) Ws[i >> 6][i & 63] = linW[i];
    int r0 = (t >> 4) * 4;
    int c0 = (t & 15) * 4;
    float acc[4][4];
    #pragma unroll
    for (int i = 0; i < 4; i++)
        #pragma unroll
        for (int j = 0; j < 4; j++) acc[i][j] = 0.f;

    for (int k0 = 0; k0 < HC; k0 += 16) {
        for (int i = t; i < 64 * 16; i += 256) {
            int m = i >> 4, k = i & 15;
            int row = row0 + m;
            As[k][m] = (row < NN) ? g_agg[row * HC + k0 + k] : 0.f;
        }
        __syncthreads();
        #pragma unroll
        for (int k = 0; k < 16; k++) {
            float4 w = *(const float4*)&Ws[k0 + k][c0];
            float a[4];
            #pragma unroll
            for (int i = 0; i < 4; i++) a[i] = As[k][r0 + i];
            #pragma unroll
            for (int i = 0; i < 4; i++) {
                acc[i][0] += a[i] * w.x; acc[i][1] += a[i] * w.y;
                acc[i][2] += a[i] * w.z; acc[i][3] += a[i] * w.w;
            }
        }
        __syncthreads();
    }
    float4 b4 = *(const float4*)&linb[c0];
    #pragma unroll
    for (int i = 0; i < 4; i++) {
        int row = row0 + r0 + i;
        if (row < NN) {
            *(float4*)&out[row * OUTC + c0] = make_float4(acc[i][0] + b4.x, acc[i][1] + b4.y,
                                                          acc[i][2] + b4.z, acc[i][3] + b4.w);
        }
    }
}

// ---------------- launcher ----------------
extern "C" void kernel_launch(void* const* d_in, const int* in_sizes, int n_in,
                              void* d_out, int out_size) {
    const float* x       = (const float*)d_in[0];
    const void*  ei      = d_in[1];
    const float* W       = (const float*)d_in[2];
    const float* att_src = (const float*)d_in[3];
    const float* att_dst = (const float*)d_in[4];
    const float* bias    = (const float*)d_in[5];
    const float* linW    = (const float*)d_in[6];
    const float* linb    = (const float*)d_in[7];
    float*       out     = (float*)d_out;

    int E  = in_sizes[1] / 2;
    int ET = E + NN;

    prep_kernel<<<(NN + 255) / 256, 256>>>((const long long*)ei);
    hist_kernel<<<(E / 4 + 256) / 256, 256>>>(ei, E);
    scan_kernel<<<1, 1024>>>();
    fill_kernel<<<(ET / 4 + 256) / 256, 256>>>(ei, E);
    gemm1_kernel<<<(NN + 127) / 128, 256>>>(x, W, att_src, att_dst);
    gather_kernel<<<(NN * 32 + 255) / 256, 256>>>(bias);
    gemm2_kernel<<<(NN + 63) / 64, 256>>>(linW, linb, out);
}

// round 10
// speedup vs baseline: 1.7872x; 1.1793x over previous
#include <cuda_runtime.h>
#include <cuda_fp16.h>

#define NN    50000
#define INC   256
#define HH    4
#define HC    128
#define OUTC  64
#define EMAX  1700000   // capacity for E + self loops

// ---------------- scratch (device globals; no allocs allowed) ----------------
__device__ __half g_h16[NN * HC];       // transformed features, fp16 (12.8 MB)
__device__ float  g_asrc[NN * HH];
__device__ float  g_adst[NN * HH];
__device__ float  g_agg[NN * HC];       // elu(agg+bias), ready for gemm2
__device__ int    g_cnt[NN];            // in-degree (incl self loop)
__device__ int    g_off[NN + 1];        // CSR offsets
__device__ int    g_cur[NN];            // fill cursors
__device__ int    g_srcidx[EMAX + NN];  // CSR column (source) indices
__device__ int    g_is64;               // edge dtype flag

// ---------------- helpers ----------------
__device__ __forceinline__ unsigned f2tf32(float f) {
    unsigned r;
    asm("cvt.rna.tf32.f32 %0, %1;" : "=r"(r) : "f"(f));
    return r;
}
__device__ __forceinline__ void mma_tf32(float c[4], const unsigned a[4], const unsigned b[2]) {
    asm volatile(
        "mma.sync.aligned.m16n8k8.row.col.f32.tf32.tf32.f32 "
        "{%0,%1,%2,%3}, {%4,%5,%6,%7}, {%8,%9}, {%0,%1,%2,%3};"
        : "+f"(c[0]), "+f"(c[1]), "+f"(c[2]), "+f"(c[3])
        : "r"(a[0]), "r"(a[1]), "r"(a[2]), "r"(a[3]), "r"(b[0]), "r"(b[1]));
}

// ---------------- fused: dtype detect (thread 0) + degree init ----------------
__global__ void prep_kernel(const long long* ei) {
    int i = blockIdx.x * blockDim.x + threadIdx.x;
    if (i == 0) {
        int ok64 = 1;
        #pragma unroll
        for (int j = 0; j < 16; j++) {
            long long v = ei[j];
            if (v < 0 || v >= (long long)NN) { ok64 = 0; break; }
        }
        g_is64 = ok64;
    }
    if (i < NN) g_cnt[i] = 1;           // self loop
}

// ---------------- GEMM1 (tf32 tensor cores) + fused attention halves ----------------
// h = x @ W  [N,256]x[256,128]; 128x128 block tile, 8 warps (4x2), 32x64 warp tile.
// Each warp's 64 cols = heads {2*wn, 2*wn+1}; att halves reduced within lane quads.
__global__ void __launch_bounds__(256) gemm1_kernel(const float* __restrict__ x,
                                                    const float* __restrict__ W,
                                                    const float* __restrict__ att_src,
                                                    const float* __restrict__ att_dst) {
    __shared__ float As[32][132];   // [k][row] tf32-rounded
    __shared__ float Bs[32][132];   // [k][col] tf32-rounded
    int t    = threadIdx.x;
    int wid  = t >> 5, lane = t & 31;
    int wm   = wid & 3, wn = wid >> 2;      // warp tile: rows wm*32.., cols wn*64..
    int qid  = lane >> 2, qtr = lane & 3;   // lane/4, lane%4
    int row0 = blockIdx.x * 128;

    float c[2][8][4];
    #pragma unroll
    for (int mf = 0; mf < 2; mf++)
        #pragma unroll
        for (int nf = 0; nf < 8; nf++)
            #pragma unroll
            for (int q = 0; q < 4; q++) c[mf][nf][q] = 0.f;

    for (int k0 = 0; k0 < INC; k0 += 32) {
        // x tile: 128 rows x 32 k  (float4 along k, transposed into As[k][row])
        #pragma unroll
        for (int r = 0; r < 4; r++) {
            int idx = t + r * 256;
            int row = idx >> 3, kq = (idx & 7) * 4;
            float4 v = make_float4(0.f, 0.f, 0.f, 0.f);
            if (row0 + row < NN) v = *(const float4*)&x[(row0 + row) * INC + k0 + kq];
            As[kq + 0][row] = __uint_as_float(f2tf32(v.x));
            As[kq + 1][row] = __uint_as_float(f2tf32(v.y));
            As[kq + 2][row] = __uint_as_float(f2tf32(v.z));
            As[kq + 3][row] = __uint_as_float(f2tf32(v.w));
        }
        // W tile: 32 k x 128 cols
        #pragma unroll
        for (int r = 0; r < 4; r++) {
            int idx = t + r * 256;
            int k = idx >> 5, nq = (idx & 31) * 4;
            float4 v = *(const float4*)&W[(k0 + k) * HC + nq];
            Bs[k][nq + 0] = __uint_as_float(f2tf32(v.x));
            Bs[k][nq + 1] = __uint_as_float(f2tf32(v.y));
            Bs[k][nq + 2] = __uint_as_float(f2tf32(v.z));
            Bs[k][nq + 3] = __uint_as_float(f2tf32(v.w));
        }
        __syncthreads();

        #pragma unroll
        for (int kk = 0; kk < 32; kk += 8) {
            unsigned a[2][4], b[8][2];
            #pragma unroll
            for (int mf = 0; mf < 2; mf++) {
                int rb = wm * 32 + mf * 16 + qid;
                a[mf][0] = __float_as_uint(As[kk + qtr][rb]);
                a[mf][1] = __float_as_uint(As[kk + qtr][rb + 8]);
                a[mf][2] = __float_as_uint(As[kk + qtr + 4][rb]);
                a[mf][3] = __float_as_uint(As[kk + qtr + 4][rb + 8]);
            }
            #pragma unroll
            for (int nf = 0; nf < 8; nf++) {
                int cb = wn * 64 + nf * 8 + qid;
                b[nf][0] = __float_as_uint(Bs[kk + qtr][cb]);
                b[nf][1] = __float_as_uint(Bs[kk + qtr + 4][cb]);
            }
            #pragma unroll
            for (int mf = 0; mf < 2; mf++)
                #pragma unroll
                for (int nf = 0; nf < 8; nf++)
                    mma_tf32(c[mf][nf], a[mf], b[nf]);
        }
        __syncthreads();
    }

    // ---- epilogue 1: store h as fp16 ----
    // D frag: c0,c1 -> row = base+qid, cols 2*qtr, 2*qtr+1; c2,c3 -> row+8.
    #pragma unroll
    for (int mf = 0; mf < 2; mf++) {
        #pragma unroll
        for (int sel = 0; sel < 2; sel++) {
            int row = row0 + wm * 32 + mf * 16 + qid + sel * 8;
            if (row < NN) {
                #pragma unroll
                for (int nf = 0; nf < 8; nf++) {
                    int col = wn * 64 + nf * 8 + 2 * qtr;
                    __half2 p = __floats2half2_rn(c[mf][nf][sel * 2], c[mf][nf][sel * 2 + 1]);
                    *(__half2*)&g_h16[row * HC + col] = p;
                }
            }
        }
    }

    // ---- epilogue 2: attention halves (two heads per warp) ----
    #pragma unroll
    for (int mf = 0; mf < 2; mf++) {
        #pragma unroll
        for (int sel = 0; sel < 2; sel++) {
            int row = row0 + wm * 32 + mf * 16 + qid + sel * 8;
            float p0s = 0.f, p0d = 0.f, p1s = 0.f, p1d = 0.f;
            #pragma unroll
            for (int nf = 0; nf < 8; nf++) {
                int col = wn * 64 + nf * 8 + 2 * qtr;
                float v0 = c[mf][nf][sel * 2], v1 = c[mf][nf][sel * 2 + 1];
                float s0 = att_src[col], s1 = att_src[col + 1];
                float d0 = att_dst[col], d1 = att_dst[col + 1];
                float ps = v0 * s0 + v1 * s1;
                float pd = v0 * d0 + v1 * d1;
                if (nf < 4) { p0s += ps; p0d += pd; }
                else        { p1s += ps; p1d += pd; }
            }
            // reduce over the 4 lanes of the quad (same row)
            p0s += __shfl_xor_sync(0xffffffffu, p0s, 1);
            p0s += __shfl_xor_sync(0xffffffffu, p0s, 2);
            p0d += __shfl_xor_sync(0xffffffffu, p0d, 1);
            p0d += __shfl_xor_sync(0xffffffffu, p0d, 2);
            p1s += __shfl_xor_sync(0xffffffffu, p1s, 1);
            p1s += __shfl_xor_sync(0xffffffffu, p1s, 2);
            p1d += __shfl_xor_sync(0xffffffffu, p1d, 1);
            p1d += __shfl_xor_sync(0xffffffffu, p1d, 2);
            if (qtr == 0 && row < NN) {
                int hd = wn * 2;
                g_asrc[row * HH + hd]     = p0s;
                g_adst[row * HH + hd]     = p0d;
                g_asrc[row * HH + hd + 1] = p1s;
                g_adst[row * HH + hd + 1] = p1d;
            }
        }
    }
}

// ---------------- CSR build: histogram (simple: 1 edge/thread) ----------------
__global__ void hist_kernel(const void* __restrict__ ei, int E) {
    int e = blockIdx.x * blockDim.x + threadIdx.x;
    if (e >= E) return;
    int d;
    if (g_is64) d = (int)((const long long*)ei)[E + e];
    else        d = ((const int*)ei)[E + e];
    atomicAdd(&g_cnt[d], 1);
}

// ---------------- CSR build: single-block exclusive scan ----------------
__global__ void __launch_bounds__(1024) scan_kernel() {
    __shared__ int partial[1024];
    const int PER = (NN + 1023) / 1024;     // 49
    int t = threadIdx.x;
    int base = t * PER;
    int sum = 0;
    for (int i = 0; i < PER; i++) {
        int idx = base + i;
        if (idx < NN) sum += g_cnt[idx];
    }
    partial[t] = sum;
    __syncthreads();
    for (int off = 1; off < 1024; off <<= 1) {
        int v = (t >= off) ? partial[t - off] : 0;
        __syncthreads();
        partial[t] += v;
        __syncthreads();
    }
    int run = partial[t] - sum;
    for (int i = 0; i < PER; i++) {
        int idx = base + i;
        if (idx < NN) {
            int c = g_cnt[idx];
            g_off[idx] = run;
            g_cur[idx] = run;
            run += c;
        }
    }
    if (t == 1023) g_off[NN] = partial[1023];
}

// ---------------- CSR build: fill (simple: 1 edge/thread) ----------------
__global__ void fill_kernel(const void* __restrict__ ei, int E) {
    int e = blockIdx.x * blockDim.x + threadIdx.x;
    int ET = E + NN;
    if (e >= ET) return;
    int s, d;
    if (e >= E) { s = d = e - E; }
    else if (g_is64) {
        const long long* p = (const long long*)ei;
        s = (int)p[e]; d = (int)p[E + e];
    } else {
        const int* p = (const int*)ei;
        s = p[e]; d = p[E + e];
    }
    int pos = atomicAdd(&g_cur[d], 1);
    g_srcidx[pos] = s;
}

// ---------------- fused gather: softmax + weighted sum + bias + ELU ----------------
// warp per destination node; lane owns 4 feature channels (8B fp16); head = lane>>3.
__global__ void gather_kernel(const float* __restrict__ bias) {
    int gid  = blockIdx.x * blockDim.x + threadIdx.x;
    int node = gid >> 5;
    int lane = gid & 31;
    if (node >= NN) return;
    int beg = g_off[node], end = g_off[node + 1];
    int h = lane >> 3;
    float adst = g_adst[node * HH + h];
    float a0 = 0.f, a1 = 0.f, a2 = 0.f, a3 = 0.f, den = 0.f;

    int k = beg;
    for (; k + 1 < end; k += 2) {
        int sA = __ldg(&g_srcidx[k]);
        int sB = __ldg(&g_srcidx[k + 1]);
        float asA = __ldg(&g_asrc[sA * HH + h]);
        float asB = __ldg(&g_asrc[sB * HH + h]);
        uint2 rA = *(const uint2*)&g_h16[sA * HC + lane * 4];
        uint2 rB = *(const uint2*)&g_h16[sB * HC + lane * 4];
        float2 hA0 = __half22float2(*(__half2*)&rA.x);
        float2 hA1 = __half22float2(*(__half2*)&rA.y);
        float2 hB0 = __half22float2(*(__half2*)&rB.x);
        float2 hB1 = __half22float2(*(__half2*)&rB.y);
        float avA = asA + adst; avA = avA > 0.f ? avA : 0.2f * avA;
        float avB = asB + adst; avB = avB > 0.f ? avB : 0.2f * avB;
        float exA = __expf(avA);
        float exB = __expf(avB);
        a0 += exA * hA0.x + exB * hB0.x;
        a1 += exA * hA0.y + exB * hB0.y;
        a2 += exA * hA1.x + exB * hB1.x;
        a3 += exA * hA1.y + exB * hB1.y;
        den += exA + exB;
    }
    if (k < end) {
        int sA = __ldg(&g_srcidx[k]);
        float asA = __ldg(&g_asrc[sA * HH + h]);
        uint2 rA = *(const uint2*)&g_h16[sA * HC + lane * 4];
        float2 hA0 = __half22float2(*(__half2*)&rA.x);
        float2 hA1 = __half22float2(*(__half2*)&rA.y);
        float avA = asA + adst; avA = avA > 0.f ? avA : 0.2f * avA;
        float exA = __expf(avA);
        a0 += exA * hA0.x; a1 += exA * hA0.y; a2 += exA * hA1.x; a3 += exA * hA1.y;
        den += exA;
    }

    float inv = 1.f / den;                   // self loop guarantees den > 0
    float4 b = *(const float4*)&bias[lane * 4];
    float v0 = a0 * inv + b.x, v1 = a1 * inv + b.y;
    float v2 = a2 * inv + b.z, v3 = a3 * inv + b.w;
    v0 = v0 > 0.f ? v0 : expm1f(v0);
    v1 = v1 > 0.f ? v1 : expm1f(v1);
    v2 = v2 > 0.f ? v2 : expm1f(v2);
    v3 = v3 > 0.f ? v3 : expm1f(v3);
    *(float4*)&g_agg[node * HC + lane * 4] = make_float4(v0, v1, v2, v3);
}

// ---------------- GEMM2: out = g_agg @ lin_W + lin_b ----------------
__global__ void __launch_bounds__(256) gemm2_kernel(const float* __restrict__ linW,
                                                    const float* __restrict__ linb,
                                                    float* __restrict__ out) {
    __shared__ float As2[16][65];
    __shared__ float Ws[HC][OUTC];
    int t    = threadIdx.x;
    int row0 = blockIdx.x * 64;
    for (int i = t; i < HC * OUTC; i += 256) Ws[i >> 6][i & 63] = linW[i];
    int r0 = (t >> 4) * 4;
    int c0 = (t & 15) * 4;
    float acc[4][4];
    #pragma unroll
    for (int i = 0; i < 4; i++)
        #pragma unroll
        for (int j = 0; j < 4; j++) acc[i][j] = 0.f;

    for (int k0 = 0; k0 < HC; k0 += 16) {
        for (int i = t; i < 64 * 16; i += 256) {
            int m = i >> 4, k = i & 15;
            int row = row0 + m;
            As2[k][m] = (row < NN) ? g_agg[row * HC + k0 + k] : 0.f;
        }
        __syncthreads();
        #pragma unroll
        for (int k = 0; k < 16; k++) {
            float4 w = *(const float4*)&Ws[k0 + k][c0];
            float a[4];
            #pragma unroll
            for (int i = 0; i < 4; i++) a[i] = As2[k][r0 + i];
            #pragma unroll
            for (int i = 0; i < 4; i++) {
                acc[i][0] += a[i] * w.x; acc[i][1] += a[i] * w.y;
                acc[i][2] += a[i] * w.z; acc[i][3] += a[i] * w.w;
            }
        }
        __syncthreads();
    }
    float4 b4 = *(const float4*)&linb[c0];
    #pragma unroll
    for (int i = 0; i < 4; i++) {
        int row = row0 + r0 + i;
        if (row < NN) {
            *(float4*)&out[row * OUTC + c0] = make_float4(acc[i][0] + b4.x, acc[i][1] + b4.y,
                                                          acc[i][2] + b4.z, acc[i][3] + b4.w);
        }
    }
}

// ---------------- launcher ----------------
extern "C" void kernel_launch(void* const* d_in, const int* in_sizes, int n_in,
                              void* d_out, int out_size) {
    const float* x       = (const float*)d_in[0];
    const void*  ei      = d_in[1];
    const float* W       = (const float*)d_in[2];
    const float* att_src = (const float*)d_in[3];
    const float* att_dst = (const float*)d_in[4];
    const float* bias    = (const float*)d_in[5];
    const float* linW    = (const float*)d_in[6];
    const float* linb    = (const float*)d_in[7];
    float*       out     = (float*)d_out;

    int E  = in_sizes[1] / 2;
    int ET = E + NN;

    prep_kernel<<<(NN + 255) / 256, 256>>>((const long long*)ei);
    hist_kernel<<<(E + 255) / 256, 256>>>(ei, E);
    scan_kernel<<<1, 1024>>>();
    fill_kernel<<<(ET + 255) / 256, 256>>>(ei, E);
    gemm1_kernel<<<(NN + 127) / 128, 256>>>(x, W, att_src, att_dst);
    gather_kernel<<<(NN * 32 + 255) / 256, 256>>>(bias);
    gemm2_kernel<<<(NN + 63) / 64, 256>>>(linW, linb, out);
}

// round 14
// speedup vs baseline: 2.1768x; 1.2180x over previous
#include <cuda_runtime.h>
#include <cuda_fp16.h>

#define NN    50000
#define INC   256
#define HH    4
#define HC    128
#define OUTC  64
#define EMAX  1700000   // capacity for E + self loops

// ---------------- scratch (device globals; no allocs allowed) ----------------
__device__ __half g_h16[NN * HC];       // transformed features, fp16 (12.8 MB)
__device__ float  g_asrc[NN * HH];
__device__ float  g_adst[NN * HH];
__device__ float  g_agg[NN * HC];       // elu(agg+bias), input to gemm2
__device__ int    g_cnt[NN];            // in-degree (incl self loop)
__device__ int    g_off[NN + 1];        // CSR offsets
__device__ int    g_rank[EMAX];         // per-edge slot within its dst bucket
__device__ int    g_srcidx[EMAX + NN];  // CSR column (source) indices
__device__ int    g_is64;               // edge dtype flag

// ---------------- helpers ----------------
__device__ __forceinline__ unsigned f2tf32(float f) {
    unsigned r;
    asm("cvt.rna.tf32.f32 %0, %1;" : "=r"(r) : "f"(f));
    return r;
}
__device__ __forceinline__ void mma_tf32(float c[4], const unsigned a[4], const unsigned b[2]) {
    asm volatile(
        "mma.sync.aligned.m16n8k8.row.col.f32.tf32.tf32.f32 "
        "{%0,%1,%2,%3}, {%4,%5,%6,%7}, {%8,%9}, {%0,%1,%2,%3};"
        : "+f"(c[0]), "+f"(c[1]), "+f"(c[2]), "+f"(c[3])
        : "r"(a[0]), "r"(a[1]), "r"(a[2]), "r"(a[3]), "r"(b[0]), "r"(b[1]));
}

// ---------------- fused: dtype detect (thread 0) + degree init ----------------
__global__ void prep_kernel(const long long* ei) {
    int i = blockIdx.x * blockDim.x + threadIdx.x;
    if (i == 0) {
        int ok64 = 1;
        #pragma unroll
        for (int j = 0; j < 16; j++) {
            long long v = ei[j];
            if (v < 0 || v >= (long long)NN) { ok64 = 0; break; }
        }
        g_is64 = ok64;
    }
    if (i < NN) g_cnt[i] = 1;           // self loop reserves slot 0
}

// ---------------- CSR build: histogram + rank (one atomic per edge total) ----------------
__global__ void hist_kernel(const void* __restrict__ ei, int E) {
    int e = blockIdx.x * blockDim.x + threadIdx.x;
    if (e >= E) return;
    int d;
    if (g_is64) d = (int)((const long long*)ei)[E + e];
    else        d = ((const int*)ei)[E + e];
    g_rank[e] = atomicAdd(&g_cnt[d], 1);    // returns slot >= 1
}

// ---------------- CSR build: single-block exclusive scan ----------------
__global__ void __launch_bounds__(1024) scan_kernel() {
    __shared__ int partial[1024];
    const int PER = (NN + 1023) / 1024;     // 49
    int t = threadIdx.x;
    int base = t * PER;
    int sum = 0;
    for (int i = 0; i < PER; i++) {
        int idx = base + i;
        if (idx < NN) sum += g_cnt[idx];
    }
    partial[t] = sum;
    __syncthreads();
    for (int off = 1; off < 1024; off <<= 1) {
        int v = (t >= off) ? partial[t - off] : 0;
        __syncthreads();
        partial[t] += v;
        __syncthreads();
    }
    int run = partial[t] - sum;
    for (int i = 0; i < PER; i++) {
        int idx = base + i;
        if (idx < NN) {
            g_off[idx] = run;
            run += g_cnt[idx];
        }
    }
    if (t == 1023) g_off[NN] = partial[1023];
}

// ---------------- CSR build: fill (atomic-free) ----------------
__global__ void fill_kernel(const void* __restrict__ ei, int E) {
    int e = blockIdx.x * blockDim.x + threadIdx.x;
    int ET = E + NN;
    if (e >= ET) return;
    if (e >= E) {                            // self loop -> slot 0
        int i = e - E;
        g_srcidx[g_off[i]] = i;
        return;
    }
    int s, d;
    if (g_is64) {
        const long long* p = (const long long*)ei;
        s = (int)p[e]; d = (int)p[E + e];
    } else {
        const int* p = (const int*)ei;
        s = p[e]; d = p[E + e];
    }
    g_srcidx[g_off[d] + g_rank[e]] = s;
}

// ---------------- GEMM1 (tf32 tensor cores) + fused attention halves ----------------
// h = x @ W  [N,256]x[256,128]; 128x128 block tile, 8 warps (4x2), 32x64 warp tile.
__global__ void __launch_bounds__(256) gemm1_kernel(const float* __restrict__ x,
                                                    const float* __restrict__ W,
                                                    const float* __restrict__ att_src,
                                                    const float* __restrict__ att_dst) {
    __shared__ float As[32][132];   // [k][row] tf32-rounded
    __shared__ float Bs[32][132];   // [k][col] tf32-rounded
    int t    = threadIdx.x;
    int wid  = t >> 5, lane = t & 31;
    int wm   = wid & 3, wn = wid >> 2;      // warp tile: rows wm*32.., cols wn*64..
    int qid  = lane >> 2, qtr = lane & 3;
    int row0 = blockIdx.x * 128;

    float c[2][8][4];
    #pragma unroll
    for (int mf = 0; mf < 2; mf++)
        #pragma unroll
        for (int nf = 0; nf < 8; nf++)
            #pragma unroll
            for (int q = 0; q < 4; q++) c[mf][nf][q] = 0.f;

    for (int k0 = 0; k0 < INC; k0 += 32) {
        #pragma unroll
        for (int r = 0; r < 4; r++) {
            int idx = t + r * 256;
            int row = idx >> 3, kq = (idx & 7) * 4;
            float4 v = make_float4(0.f, 0.f, 0.f, 0.f);
            if (row0 + row < NN) v = *(const float4*)&x[(row0 + row) * INC + k0 + kq];
            As[kq + 0][row] = __uint_as_float(f2tf32(v.x));
            As[kq + 1][row] = __uint_as_float(f2tf32(v.y));
            As[kq + 2][row] = __uint_as_float(f2tf32(v.z));
            As[kq + 3][row] = __uint_as_float(f2tf32(v.w));
        }
        #pragma unroll
        for (int r = 0; r < 4; r++) {
            int idx = t + r * 256;
            int k = idx >> 5, nq = (idx & 31) * 4;
            float4 v = *(const float4*)&W[(k0 + k) * HC + nq];
            Bs[k][nq + 0] = __uint_as_float(f2tf32(v.x));
            Bs[k][nq + 1] = __uint_as_float(f2tf32(v.y));
            Bs[k][nq + 2] = __uint_as_float(f2tf32(v.z));
            Bs[k][nq + 3] = __uint_as_float(f2tf32(v.w));
        }
        __syncthreads();

        #pragma unroll
        for (int kk = 0; kk < 32; kk += 8) {
            unsigned a[2][4], b[8][2];
            #pragma unroll
            for (int mf = 0; mf < 2; mf++) {
                int rb = wm * 32 + mf * 16 + qid;
                a[mf][0] = __float_as_uint(As[kk + qtr][rb]);
                a[mf][1] = __float_as_uint(As[kk + qtr][rb + 8]);
                a[mf][2] = __float_as_uint(As[kk + qtr + 4][rb]);
                a[mf][3] = __float_as_uint(As[kk + qtr + 4][rb + 8]);
            }
            #pragma unroll
            for (int nf = 0; nf < 8; nf++) {
                int cb = wn * 64 + nf * 8 + qid;
                b[nf][0] = __float_as_uint(Bs[kk + qtr][cb]);
                b[nf][1] = __float_as_uint(Bs[kk + qtr + 4][cb]);
            }
            #pragma unroll
            for (int mf = 0; mf < 2; mf++)
                #pragma unroll
                for (int nf = 0; nf < 8; nf++)
                    mma_tf32(c[mf][nf], a[mf], b[nf]);
        }
        __syncthreads();
    }

    // ---- epilogue 1: store h as fp16 ----
    #pragma unroll
    for (int mf = 0; mf < 2; mf++) {
        #pragma unroll
        for (int sel = 0; sel < 2; sel++) {
            int row = row0 + wm * 32 + mf * 16 + qid + sel * 8;
            if (row < NN) {
                #pragma unroll
                for (int nf = 0; nf < 8; nf++) {
                    int col = wn * 64 + nf * 8 + 2 * qtr;
                    __half2 p = __floats2half2_rn(c[mf][nf][sel * 2], c[mf][nf][sel * 2 + 1]);
                    *(__half2*)&g_h16[row * HC + col] = p;
                }
            }
        }
    }

    // ---- epilogue 2: attention halves (two heads per warp) ----
    #pragma unroll
    for (int mf = 0; mf < 2; mf++) {
        #pragma unroll
        for (int sel = 0; sel < 2; sel++) {
            int row = row0 + wm * 32 + mf * 16 + qid + sel * 8;
            float p0s = 0.f, p0d = 0.f, p1s = 0.f, p1d = 0.f;
            #pragma unroll
            for (int nf = 0; nf < 8; nf++) {
                int col = wn * 64 + nf * 8 + 2 * qtr;
                float v0 = c[mf][nf][sel * 2], v1 = c[mf][nf][sel * 2 + 1];
                float ps = v0 * att_src[col] + v1 * att_src[col + 1];
                float pd = v0 * att_dst[col] + v1 * att_dst[col + 1];
                if (nf < 4) { p0s += ps; p0d += pd; }
                else        { p1s += ps; p1d += pd; }
            }
            p0s += __shfl_xor_sync(0xffffffffu, p0s, 1);
            p0s += __shfl_xor_sync(0xffffffffu, p0s, 2);
            p0d += __shfl_xor_sync(0xffffffffu, p0d, 1);
            p0d += __shfl_xor_sync(0xffffffffu, p0d, 2);
            p1s += __shfl_xor_sync(0xffffffffu, p1s, 1);
            p1s += __shfl_xor_sync(0xffffffffu, p1s, 2);
            p1d += __shfl_xor_sync(0xffffffffu, p1d, 1);
            p1d += __shfl_xor_sync(0xffffffffu, p1d, 2);
            if (qtr == 0 && row < NN) {
                int hd = wn * 2;
                g_asrc[row * HH + hd]     = p0s;
                g_adst[row * HH + hd]     = p0d;
                g_asrc[row * HH + hd + 1] = p1s;
                g_adst[row * HH + hd + 1] = p1d;
            }
        }
    }
}

// ---------------- fused gather: softmax + weighted sum + bias + ELU ----------------
__global__ void gather_kernel(const float* __restrict__ bias) {
    int gid  = blockIdx.x * blockDim.x + threadIdx.x;
    int node = gid >> 5;
    int lane = gid & 31;
    if (node >= NN) return;
    int beg = g_off[node], end = g_off[node + 1];
    int h = lane >> 3;
    float adst = g_adst[node * HH + h];
    float a0 = 0.f, a1 = 0.f, a2 = 0.f, a3 = 0.f, den = 0.f;

    int k = beg;
    for (; k + 1 < end; k += 2) {
        int sA = __ldg(&g_srcidx[k]);
        int sB = __ldg(&g_srcidx[k + 1]);
        float asA = __ldg(&g_asrc[sA * HH + h]);
        float asB = __ldg(&g_asrc[sB * HH + h]);
        uint2 rA = *(const uint2*)&g_h16[sA * HC + lane * 4];
        uint2 rB = *(const uint2*)&g_h16[sB * HC + lane * 4];
        float2 hA0 = __half22float2(*(__half2*)&rA.x);
        float2 hA1 = __half22float2(*(__half2*)&rA.y);
        float2 hB0 = __half22float2(*(__half2*)&rB.x);
        float2 hB1 = __half22float2(*(__half2*)&rB.y);
        float avA = asA + adst; avA = avA > 0.f ? avA : 0.2f * avA;
        float avB = asB + adst; avB = avB > 0.f ? avB : 0.2f * avB;
        float exA = __expf(avA);
        float exB = __expf(avB);
        a0 += exA * hA0.x + exB * hB0.x;
        a1 += exA * hA0.y + exB * hB0.y;
        a2 += exA * hA1.x + exB * hB1.x;
        a3 += exA * hA1.y + exB * hB1.y;
        den += exA + exB;
    }
    if (k < end) {
        int sA = __ldg(&g_srcidx[k]);
        float asA = __ldg(&g_asrc[sA * HH + h]);
        uint2 rA = *(const uint2*)&g_h16[sA * HC + lane * 4];
        float2 hA0 = __half22float2(*(__half2*)&rA.x);
        float2 hA1 = __half22float2(*(__half2*)&rA.y);
        float avA = asA + adst; avA = avA > 0.f ? avA : 0.2f * avA;
        float exA = __expf(avA);
        a0 += exA * hA0.x; a1 += exA * hA0.y; a2 += exA * hA1.x; a3 += exA * hA1.y;
        den += exA;
    }

    float inv = 1.f / den;                   // self loop guarantees den > 0
    float4 b = *(const float4*)&bias[lane * 4];
    float v0 = a0 * inv + b.x, v1 = a1 * inv + b.y;
    float v2 = a2 * inv + b.z, v3 = a3 * inv + b.w;
    v0 = v0 > 0.f ? v0 : expm1f(v0);
    v1 = v1 > 0.f ? v1 : expm1f(v1);
    v2 = v2 > 0.f ? v2 : expm1f(v2);
    v3 = v3 > 0.f ? v3 : expm1f(v3);
    *(float4*)&g_agg[node * HC + lane * 4] = make_float4(v0, v1, v2, v3);
}

// ---------------- GEMM2 (tf32): out = g_agg @ lin_W + lin_b ----------------
// 128x64 block tile, 8 warps (4x2), warp tile 32x32.
__global__ void __launch_bounds__(256) gemm2_kernel(const float* __restrict__ linW,
                                                    const float* __restrict__ linb,
                                                    float* __restrict__ out) {
    __shared__ float As[32][132];   // [k][row]
    __shared__ float Bs[32][68];    // [k][col]
    int t    = threadIdx.x;
    int wid  = t >> 5, lane = t & 31;
    int wm   = wid & 3, wn = wid >> 2;      // rows wm*32.., cols wn*32..
    int qid  = lane >> 2, qtr = lane & 3;
    int row0 = blockIdx.x * 128;

    float c[2][4][4];
    #pragma unroll
    for (int mf = 0; mf < 2; mf++)
        #pragma unroll
        for (int nf = 0; nf < 4; nf++)
            #pragma unroll
            for (int q = 0; q < 4; q++) c[mf][nf][q] = 0.f;

    for (int k0 = 0; k0 < HC; k0 += 32) {
        // agg tile: 128 rows x 32 k
        #pragma unroll
        for (int r = 0; r < 4; r++) {
            int idx = t + r * 256;
            int row = idx >> 3, kq = (idx & 7) * 4;
            float4 v = make_float4(0.f, 0.f, 0.f, 0.f);
            if (row0 + row < NN) v = *(const float4*)&g_agg[(row0 + row) * HC + k0 + kq];
            As[kq + 0][row] = __uint_as_float(f2tf32(v.x));
            As[kq + 1][row] = __uint_as_float(f2tf32(v.y));
            As[kq + 2][row] = __uint_as_float(f2tf32(v.z));
            As[kq + 3][row] = __uint_as_float(f2tf32(v.w));
        }
        // linW tile: 32 k x 64 cols
        {
            int idx = t;
            int k = idx >> 4, nq = (idx & 15) * 4;
            float4 v = *(const float4*)&linW[(k0 + k) * OUTC + nq];
            Bs[k][nq + 0] = __uint_as_float(f2tf32(v.x));
            Bs[k][nq + 1] = __uint_as_float(f2tf32(v.y));
            Bs[k][nq + 2] = __uint_as_float(f2tf32(v.z));
            Bs[k][nq + 3] = __uint_as_float(f2tf32(v.w));
            idx = t + 256;
            k = idx >> 4; nq = (idx & 15) * 4;
            v = *(const float4*)&linW[(k0 + k) * OUTC + nq];
            Bs[k][nq + 0] = __uint_as_float(f2tf32(v.x));
            Bs[k][nq + 1] = __uint_as_float(f2tf32(v.y));
            Bs[k][nq + 2] = __uint_as_float(f2tf32(v.z));
            Bs[k][nq + 3] = __uint_as_float(f2tf32(v.w));
        }
        __syncthreads();

        #pragma unroll
        for (int kk = 0; kk < 32; kk += 8) {
            unsigned a[2][4], b[4][2];
            #pragma unroll
            for (int mf = 0; mf < 2; mf++) {
                int rb = wm * 32 + mf * 16 + qid;
                a[mf][0] = __float_as_uint(As[kk + qtr][rb]);
                a[mf][1] = __float_as_uint(As[kk + qtr][rb + 8]);
                a[mf][2] = __float_as_uint(As[kk + qtr + 4][rb]);
                a[mf][3] = __float_as_uint(As[kk + qtr + 4][rb + 8]);
            }
            #pragma unroll
            for (int nf = 0; nf < 4; nf++) {
                int cb = wn * 32 + nf * 8 + qid;
                b[nf][0] = __float_as_uint(Bs[kk + qtr][cb]);
                b[nf][1] = __float_as_uint(Bs[kk + qtr + 4][cb]);
            }
            #pragma unroll
            for (int mf = 0; mf < 2; mf++)
                #pragma unroll
                for (int nf = 0; nf < 4; nf++)
                    mma_tf32(c[mf][nf], a[mf], b[nf]);
        }
        __syncthreads();
    }

    #pragma unroll
    for (int mf = 0; mf < 2; mf++) {
        #pragma unroll
        for (int sel = 0; sel < 2; sel++) {
            int row = row0 + wm * 32 + mf * 16 + qid + sel * 8;
            if (row < NN) {
                #pragma unroll
                for (int nf = 0; nf < 4; nf++) {
                    int col = wn * 32 + nf * 8 + 2 * qtr;
                    float2 v;
                    v.x = c[mf][nf][sel * 2]     + linb[col];
                    v.y = c[mf][nf][sel * 2 + 1] + linb[col + 1];
                    *(float2*)&out[row * OUTC + col] = v;
                }
            }
        }
    }
}

// ---------------- launcher ----------------
extern "C" void kernel_launch(void* const* d_in, const int* in_sizes, int n_in,
                              void* d_out, int out_size) {
    const float* x       = (const float*)d_in[0];
    const void*  ei      = d_in[1];
    const float* W       = (const float*)d_in[2];
    const float* att_src = (const float*)d_in[3];
    const float* att_dst = (const float*)d_in[4];
    const float* bias    = (const float*)d_in[5];
    const float* linW    = (const float*)d_in[6];
    const float* linb    = (const float*)d_in[7];
    float*       out     = (float*)d_out;

    int E  = in_sizes[1] / 2;
    int ET = E + NN;

    prep_kernel<<<(NN + 255) / 256, 256>>>((const long long*)ei);
    hist_kernel<<<(E + 255) / 256, 256>>>(ei, E);
    scan_kernel<<<1, 1024>>>();
    fill_kernel<<<(ET + 255) / 256, 256>>>(ei, E);
    gemm1_kernel<<<(NN + 127) / 128, 256>>>(x, W, att_src, att_dst);
    gather_kernel<<<(NN * 32 + 255) / 256, 256>>>(bias);
    gemm2_kernel<<<(NN + 127) / 128, 256>>>(linW, linb, out);
}

// round 15
// speedup vs baseline: 2.4303x; 1.1165x over previous
#include <cuda_runtime.h>
#include <cuda_fp16.h>

#define NN    50000
#define INC   256
#define HH    4
#define HC    128
#define OUTC  64
#define EMAX  1700000   // capacity for E + self loops

// ---------------- scratch (device globals; no allocs allowed) ----------------
__device__ __half g_h16[NN * HC];       // transformed features, fp16 (12.8 MB)
__device__ float  g_asrc[NN * HH];
__device__ float  g_adst[NN * HH];
__device__ float  g_agg[NN * HC];       // elu(agg+bias), input to gemm2
__device__ int    g_cnt[NN];            // in-degree (incl self loop)
__device__ int    g_off[NN + 1];        // CSR offsets
__device__ int    g_rank[EMAX];         // per-edge slot within its dst bucket
__device__ int    g_srcidx[EMAX + NN];  // CSR column (source) indices
__device__ int    g_is64;               // edge dtype flag

// ---------------- helpers ----------------
__device__ __forceinline__ unsigned f2tf32(float f) {
    unsigned r;
    asm("cvt.rna.tf32.f32 %0, %1;" : "=r"(r) : "f"(f));
    return r;
}
__device__ __forceinline__ void mma_tf32(float c[4], const unsigned a[4], const unsigned b[2]) {
    asm volatile(
        "mma.sync.aligned.m16n8k8.row.col.f32.tf32.tf32.f32 "
        "{%0,%1,%2,%3}, {%4,%5,%6,%7}, {%8,%9}, {%0,%1,%2,%3};"
        : "+f"(c[0]), "+f"(c[1]), "+f"(c[2]), "+f"(c[3])
        : "r"(a[0]), "r"(a[1]), "r"(a[2]), "r"(a[3]), "r"(b[0]), "r"(b[1]));
}

// ---------------- fused: dtype detect (thread 0) + degree init ----------------
__global__ void prep_kernel(const long long* ei) {
    int i = blockIdx.x * blockDim.x + threadIdx.x;
    if (i == 0) {
        int ok64 = 1;
        #pragma unroll
        for (int j = 0; j < 16; j++) {
            long long v = ei[j];
            if (v < 0 || v >= (long long)NN) { ok64 = 0; break; }
        }
        g_is64 = ok64;
    }
    if (i < NN) g_cnt[i] = 1;           // self loop reserves slot 0
}

// ---------------- CSR build: histogram + rank (one atomic per edge total) ----------------
__global__ void hist_kernel(const void* __restrict__ ei, int E) {
    int e = blockIdx.x * blockDim.x + threadIdx.x;
    if (e >= E) return;
    int d;
    if (g_is64) d = (int)((const long long*)ei)[E + e];
    else        d = ((const int*)ei)[E + e];
    g_rank[e] = atomicAdd(&g_cnt[d], 1);    // returns slot >= 1
}

// ---------------- CSR build: single-block exclusive scan ----------------
__global__ void __launch_bounds__(1024) scan_kernel() {
    __shared__ int partial[1024];
    const int PER = (NN + 1023) / 1024;     // 49
    int t = threadIdx.x;
    int base = t * PER;
    int sum = 0;
    for (int i = 0; i < PER; i++) {
        int idx = base + i;
        if (idx < NN) sum += g_cnt[idx];
    }
    partial[t] = sum;
    __syncthreads();
    for (int off = 1; off < 1024; off <<= 1) {
        int v = (t >= off) ? partial[t - off] : 0;
        __syncthreads();
        partial[t] += v;
        __syncthreads();
    }
    int run = partial[t] - sum;
    for (int i = 0; i < PER; i++) {
        int idx = base + i;
        if (idx < NN) {
            g_off[idx] = run;
            run += g_cnt[idx];
        }
    }
    if (t == 1023) g_off[NN] = partial[1023];
}

// ---------------- CSR build: fill (atomic-free) ----------------
__global__ void fill_kernel(const void* __restrict__ ei, int E) {
    int e = blockIdx.x * blockDim.x + threadIdx.x;
    int ET = E + NN;
    if (e >= ET) return;
    if (e >= E) {                            // self loop -> slot 0
        int i = e - E;
        g_srcidx[g_off[i]] = i;
        return;
    }
    int s, d;
    if (g_is64) {
        const long long* p = (const long long*)ei;
        s = (int)p[e]; d = (int)p[E + e];
    } else {
        const int* p = (const int*)ei;
        s = p[e]; d = p[E + e];
    }
    g_srcidx[g_off[d] + g_rank[e]] = s;
}

// ---------------- GEMM1 (tf32 tensor cores) + fused attention halves ----------------
__global__ void __launch_bounds__(256) gemm1_kernel(const float* __restrict__ x,
                                                    const float* __restrict__ W,
                                                    const float* __restrict__ att_src,
                                                    const float* __restrict__ att_dst) {
    __shared__ float As[32][132];   // [k][row] tf32-rounded
    __shared__ float Bs[32][132];   // [k][col] tf32-rounded
    int t    = threadIdx.x;
    int wid  = t >> 5, lane = t & 31;
    int wm   = wid & 3, wn = wid >> 2;      // warp tile: rows wm*32.., cols wn*64..
    int qid  = lane >> 2, qtr = lane & 3;
    int row0 = blockIdx.x * 128;

    float c[2][8][4];
    #pragma unroll
    for (int mf = 0; mf < 2; mf++)
        #pragma unroll
        for (int nf = 0; nf < 8; nf++)
            #pragma unroll
            for (int q = 0; q < 4; q++) c[mf][nf][q] = 0.f;

    for (int k0 = 0; k0 < INC; k0 += 32) {
        #pragma unroll
        for (int r = 0; r < 4; r++) {
            int idx = t + r * 256;
            int row = idx >> 3, kq = (idx & 7) * 4;
            float4 v = make_float4(0.f, 0.f, 0.f, 0.f);
            if (row0 + row < NN) v = *(const float4*)&x[(row0 + row) * INC + k0 + kq];
            As[kq + 0][row] = __uint_as_float(f2tf32(v.x));
            As[kq + 1][row] = __uint_as_float(f2tf32(v.y));
            As[kq + 2][row] = __uint_as_float(f2tf32(v.z));
            As[kq + 3][row] = __uint_as_float(f2tf32(v.w));
        }
        #pragma unroll
        for (int r = 0; r < 4; r++) {
            int idx = t + r * 256;
            int k = idx >> 5, nq = (idx & 31) * 4;
            float4 v = *(const float4*)&W[(k0 + k) * HC + nq];
            Bs[k][nq + 0] = __uint_as_float(f2tf32(v.x));
            Bs[k][nq + 1] = __uint_as_float(f2tf32(v.y));
            Bs[k][nq + 2] = __uint_as_float(f2tf32(v.z));
            Bs[k][nq + 3] = __uint_as_float(f2tf32(v.w));
        }
        __syncthreads();

        #pragma unroll
        for (int kk = 0; kk < 32; kk += 8) {
            unsigned a[2][4], b[8][2];
            #pragma unroll
            for (int mf = 0; mf < 2; mf++) {
                int rb = wm * 32 + mf * 16 + qid;
                a[mf][0] = __float_as_uint(As[kk + qtr][rb]);
                a[mf][1] = __float_as_uint(As[kk + qtr][rb + 8]);
                a[mf][2] = __float_as_uint(As[kk + qtr + 4][rb]);
                a[mf][3] = __float_as_uint(As[kk + qtr + 4][rb + 8]);
            }
            #pragma unroll
            for (int nf = 0; nf < 8; nf++) {
                int cb = wn * 64 + nf * 8 + qid;
                b[nf][0] = __float_as_uint(Bs[kk + qtr][cb]);
                b[nf][1] = __float_as_uint(Bs[kk + qtr + 4][cb]);
            }
            #pragma unroll
            for (int mf = 0; mf < 2; mf++)
                #pragma unroll
                for (int nf = 0; nf < 8; nf++)
                    mma_tf32(c[mf][nf], a[mf], b[nf]);
        }
        __syncthreads();
    }

    // ---- epilogue 1: store h as fp16 ----
    #pragma unroll
    for (int mf = 0; mf < 2; mf++) {
        #pragma unroll
        for (int sel = 0; sel < 2; sel++) {
            int row = row0 + wm * 32 + mf * 16 + qid + sel * 8;
            if (row < NN) {
                #pragma unroll
                for (int nf = 0; nf < 8; nf++) {
                    int col = wn * 64 + nf * 8 + 2 * qtr;
                    __half2 p = __floats2half2_rn(c[mf][nf][sel * 2], c[mf][nf][sel * 2 + 1]);
                    *(__half2*)&g_h16[row * HC + col] = p;
                }
            }
        }
    }

    // ---- epilogue 2: attention halves (two heads per warp) ----
    #pragma unroll
    for (int mf = 0; mf < 2; mf++) {
        #pragma unroll
        for (int sel = 0; sel < 2; sel++) {
            int row = row0 + wm * 32 + mf * 16 + qid + sel * 8;
            float p0s = 0.f, p0d = 0.f, p1s = 0.f, p1d = 0.f;
            #pragma unroll
            for (int nf = 0; nf < 8; nf++) {
                int col = wn * 64 + nf * 8 + 2 * qtr;
                float v0 = c[mf][nf][sel * 2], v1 = c[mf][nf][sel * 2 + 1];
                float ps = v0 * att_src[col] + v1 * att_src[col + 1];
                float pd = v0 * att_dst[col] + v1 * att_dst[col + 1];
                if (nf < 4) { p0s += ps; p0d += pd; }
                else        { p1s += ps; p1d += pd; }
            }
            p0s += __shfl_xor_sync(0xffffffffu, p0s, 1);
            p0s += __shfl_xor_sync(0xffffffffu, p0s, 2);
            p0d += __shfl_xor_sync(0xffffffffu, p0d, 1);
            p0d += __shfl_xor_sync(0xffffffffu, p0d, 2);
            p1s += __shfl_xor_sync(0xffffffffu, p1s, 1);
            p1s += __shfl_xor_sync(0xffffffffu, p1s, 2);
            p1d += __shfl_xor_sync(0xffffffffu, p1d, 1);
            p1d += __shfl_xor_sync(0xffffffffu, p1d, 2);
            if (qtr == 0 && row < NN) {
                int hd = wn * 2;
                g_asrc[row * HH + hd]     = p0s;
                g_adst[row * HH + hd]     = p0d;
                g_asrc[row * HH + hd + 1] = p1s;
                g_adst[row * HH + hd + 1] = p1d;
            }
        }
    }
}

// ---------------- fused gather: softmax + weighted sum + bias + ELU ----------------
// warp per destination node; lane owns 4 feature channels; head = lane>>3.
// 4-edge unroll: all loads issued before any consume -> ~12 loads in flight/lane.
__global__ void gather_kernel(const float* __restrict__ bias) {
    int gid  = blockIdx.x * blockDim.x + threadIdx.x;
    int node = gid >> 5;
    int lane = gid & 31;
    if (node >= NN) return;
    int beg = g_off[node], end = g_off[node + 1];
    int h = lane >> 3;
    float adst = g_adst[node * HH + h];
    float a0 = 0.f, a1 = 0.f, a2 = 0.f, a3 = 0.f, den = 0.f;

    int k = beg;
    for (; k + 3 < end; k += 4) {
        int   s0 = __ldg(&g_srcidx[k]);
        int   s1 = __ldg(&g_srcidx[k + 1]);
        int   s2 = __ldg(&g_srcidx[k + 2]);
        int   s3 = __ldg(&g_srcidx[k + 3]);
        float as0 = __ldg(&g_asrc[s0 * HH + h]);
        float as1 = __ldg(&g_asrc[s1 * HH + h]);
        float as2 = __ldg(&g_asrc[s2 * HH + h]);
        float as3 = __ldg(&g_asrc[s3 * HH + h]);
        uint2 r0 = *(const uint2*)&g_h16[s0 * HC + lane * 4];
        uint2 r1 = *(const uint2*)&g_h16[s1 * HC + lane * 4];
        uint2 r2 = *(const uint2*)&g_h16[s2 * HC + lane * 4];
        uint2 r3 = *(const uint2*)&g_h16[s3 * HC + lane * 4];
        float av0 = as0 + adst; av0 = av0 > 0.f ? av0 : 0.2f * av0;
        float av1 = as1 + adst; av1 = av1 > 0.f ? av1 : 0.2f * av1;
        float av2 = as2 + adst; av2 = av2 > 0.f ? av2 : 0.2f * av2;
        float av3 = as3 + adst; av3 = av3 > 0.f ? av3 : 0.2f * av3;
        float e0 = __expf(av0), e1 = __expf(av1), e2 = __expf(av2), e3 = __expf(av3);
        float2 p;
        p = __half22float2(*(__half2*)&r0.x); a0 += e0 * p.x; a1 += e0 * p.y;
        p = __half22float2(*(__half2*)&r0.y); a2 += e0 * p.x; a3 += e0 * p.y;
        p = __half22float2(*(__half2*)&r1.x); a0 += e1 * p.x; a1 += e1 * p.y;
        p = __half22float2(*(__half2*)&r1.y); a2 += e1 * p.x; a3 += e1 * p.y;
        p = __half22float2(*(__half2*)&r2.x); a0 += e2 * p.x; a1 += e2 * p.y;
        p = __half22float2(*(__half2*)&r2.y); a2 += e2 * p.x; a3 += e2 * p.y;
        p = __half22float2(*(__half2*)&r3.x); a0 += e3 * p.x; a1 += e3 * p.y;
        p = __half22float2(*(__half2*)&r3.y); a2 += e3 * p.x; a3 += e3 * p.y;
        den += (e0 + e1) + (e2 + e3);
    }
    for (; k < end; k++) {
        int sA = __ldg(&g_srcidx[k]);
        float asA = __ldg(&g_asrc[sA * HH + h]);
        uint2 rA = *(const uint2*)&g_h16[sA * HC + lane * 4];
        float avA = asA + adst; avA = avA > 0.f ? avA : 0.2f * avA;
        float exA = __expf(avA);
        float2 p;
        p = __half22float2(*(__half2*)&rA.x); a0 += exA * p.x; a1 += exA * p.y;
        p = __half22float2(*(__half2*)&rA.y); a2 += exA * p.x; a3 += exA * p.y;
        den += exA;
    }

    float inv = 1.f / den;                   // self loop guarantees den > 0
    float4 b = *(const float4*)&bias[lane * 4];
    float v0 = a0 * inv + b.x, v1 = a1 * inv + b.y;
    float v2 = a2 * inv + b.z, v3 = a3 * inv + b.w;
    v0 = v0 > 0.f ? v0 : expm1f(v0);
    v1 = v1 > 0.f ? v1 : expm1f(v1);
    v2 = v2 > 0.f ? v2 : expm1f(v2);
    v3 = v3 > 0.f ? v3 : expm1f(v3);
    *(float4*)&g_agg[node * HC + lane * 4] = make_float4(v0, v1, v2, v3);
}

// ---------------- GEMM2 (tf32): out = g_agg @ lin_W + lin_b ----------------
__global__ void __launch_bounds__(256) gemm2_kernel(const float* __restrict__ linW,
                                                    const float* __restrict__ linb,
                                                    float* __restrict__ out) {
    __shared__ float As[32][132];   // [k][row]
    __shared__ float Bs[32][68];    // [k][col]
    int t    = threadIdx.x;
    int wid  = t >> 5, lane = t & 31;
    int wm   = wid & 3, wn = wid >> 2;      // rows wm*32.., cols wn*32..
    int qid  = lane >> 2, qtr = lane & 3;
    int row0 = blockIdx.x * 128;

    float c[2][4][4];
    #pragma unroll
    for (int mf = 0; mf < 2; mf++)
        #pragma unroll
        for (int nf = 0; nf < 4; nf++)
            #pragma unroll
            for (int q = 0; q < 4; q++) c[mf][nf][q] = 0.f;

    for (int k0 = 0; k0 < HC; k0 += 32) {
        #pragma unroll
        for (int r = 0; r < 4; r++) {
            int idx = t + r * 256;
            int row = idx >> 3, kq = (idx & 7) * 4;
            float4 v = make_float4(0.f, 0.f, 0.f, 0.f);
            if (row0 + row < NN) v = *(const float4*)&g_agg[(row0 + row) * HC + k0 + kq];
            As[kq + 0][row] = __uint_as_float(f2tf32(v.x));
            As[kq + 1][row] = __uint_as_float(f2tf32(v.y));
            As[kq + 2][row] = __uint_as_float(f2tf32(v.z));
            As[kq + 3][row] = __uint_as_float(f2tf32(v.w));
        }
        {
            int idx = t;
            int k = idx >> 4, nq = (idx & 15) * 4;
            float4 v = *(const float4*)&linW[(k0 + k) * OUTC + nq];
            Bs[k][nq + 0] = __uint_as_float(f2tf32(v.x));
            Bs[k][nq + 1] = __uint_as_float(f2tf32(v.y));
            Bs[k][nq + 2] = __uint_as_float(f2tf32(v.z));
            Bs[k][nq + 3] = __uint_as_float(f2tf32(v.w));
            idx = t + 256;
            k = idx >> 4; nq = (idx & 15) * 4;
            v = *(const float4*)&linW[(k0 + k) * OUTC + nq];
            Bs[k][nq + 0] = __uint_as_float(f2tf32(v.x));
            Bs[k][nq + 1] = __uint_as_float(f2tf32(v.y));
            Bs[k][nq + 2] = __uint_as_float(f2tf32(v.z));
            Bs[k][nq + 3] = __uint_as_float(f2tf32(v.w));
        }
        __syncthreads();

        #pragma unroll
        for (int kk = 0; kk < 32; kk += 8) {
            unsigned a[2][4], b[4][2];
            #pragma unroll
            for (int mf = 0; mf < 2; mf++) {
                int rb = wm * 32 + mf * 16 + qid;
                a[mf][0] = __float_as_uint(As[kk + qtr][rb]);
                a[mf][1] = __float_as_uint(As[kk + qtr][rb + 8]);
                a[mf][2] = __float_as_uint(As[kk + qtr + 4][rb]);
                a[mf][3] = __float_as_uint(As[kk + qtr + 4][rb + 8]);
            }
            #pragma unroll
            for (int nf = 0; nf < 4; nf++) {
                int cb = wn * 32 + nf * 8 + qid;
                b[nf][0] = __float_as_uint(Bs[kk + qtr][cb]);
                b[nf][1] = __float_as_uint(Bs[kk + qtr + 4][cb]);
            }
            #pragma unroll
            for (int mf = 0; mf < 2; mf++)
                #pragma unroll
                for (int nf = 0; nf < 4; nf++)
                    mma_tf32(c[mf][nf], a[mf], b[nf]);
        }
        __syncthreads();
    }

    #pragma unroll
    for (int mf = 0; mf < 2; mf++) {
        #pragma unroll
        for (int sel = 0; sel < 2; sel++) {
            int row = row0 + wm * 32 + mf * 16 + qid + sel * 8;
            if (row < NN) {
                #pragma unroll
                for (int nf = 0; nf < 4; nf++) {
                    int col = wn * 32 + nf * 8 + 2 * qtr;
                    float2 v;
                    v.x = c[mf][nf][sel * 2]     + linb[col];
                    v.y = c[mf][nf][sel * 2 + 1] + linb[col + 1];
                    *(float2*)&out[row * OUTC + col] = v;
                }
            }
        }
    }
}

// ---------------- launcher: CSR build on default stream, gemm1 forked ----------------
extern "C" void kernel_launch(void* const* d_in, const int* in_sizes, int n_in,
                              void* d_out, int out_size) {
    const float* x       = (const float*)d_in[0];
    const void*  ei      = d_in[1];
    const float* W       = (const float*)d_in[2];
    const float* att_src = (const float*)d_in[3];
    const float* att_dst = (const float*)d_in[4];
    const float* bias    = (const float*)d_in[5];
    const float* linW    = (const float*)d_in[6];
    const float* linb    = (const float*)d_in[7];
    float*       out     = (float*)d_out;

    int E  = in_sizes[1] / 2;
    int ET = E + NN;

    // Lazily created host-side objects (no device memory). First call happens
    // outside graph capture (correctness run), so creation is never captured.
    static cudaStream_t s2 = nullptr;
    static cudaEvent_t  evFork = nullptr, evJoin = nullptr;
    if (s2 == nullptr) {
        cudaStreamCreateWithFlags(&s2, cudaStreamNonBlocking);
        cudaEventCreateWithFlags(&evFork, cudaEventDisableTiming);
        cudaEventCreateWithFlags(&evJoin, cudaEventDisableTiming);
    }

    // fork: gemm1 (tensor-bound) overlaps the CSR build chain (latency-bound)
    cudaEventRecord(evFork, 0);
    cudaStreamWaitEvent(s2, evFork, 0);
    gemm1_kernel<<<(NN + 127) / 128, 256, 0, s2>>>(x, W, att_src, att_dst);
    cudaEventRecord(evJoin, s2);

    prep_kernel<<<(NN + 255) / 256, 256>>>((const long long*)ei);
    hist_kernel<<<(E + 255) / 256, 256>>>(ei, E);
    scan_kernel<<<1, 1024>>>();
    fill_kernel<<<(ET + 255) / 256, 256>>>(ei, E);

    // join: gather needs both the CSR and gemm1 outputs
    cudaStreamWaitEvent(0, evJoin, 0);
    gather_kernel<<<(NN * 32 + 255) / 256, 256>>>(bias);
    gemm2_kernel<<<(NN + 127) / 128, 256>>>(linW, linb, out);
}